// round 11
// baseline (speedup 1.0000x reference)
#include <cuda_runtime.h>
#include <cstdint>

// Problem shape (fixed by the reference)
#define BATCH 64
#define SEQ   8
#define VOCAB 128000

// 25 splits/row -> 1600 blocks of 256 threads (8 warps).
// Each split: 5120 floats = 1280 float4 -> exactly 5 float4 per thread.
#define SPLITS       25
#define THREADS      256
#define SPLIT_FLOATS (VOCAB / SPLITS)       // 5120
#define SPLIT_F4     (SPLIT_FLOATS / 4)     // 1280
#define F4_PER_THR   (SPLIT_F4 / THREADS)   // 5

// Scratch (no cudaMalloc allowed). g_count starts 0 and is reset by the
// last-arriving block each run -> deterministic across graph replays.
__device__ float g_pmax[BATCH * SPLITS];
__device__ int   g_pidx[BATCH * SPLITS];
__device__ int   g_count[BATCH];

__device__ __forceinline__ void take_better(float v, int i, float& bm, int& bi) {
    // full tie-break (first occurrence = smaller index) for cross-thread merge
    if (v > bm || (v == bm && i < bi)) { bm = v; bi = i; }
}

// In-thread scan: this thread's element indices strictly increase, so strict >
// keeps first occurrence. fmaxf tree for ILP; index recovered on rare update.
__device__ __forceinline__ void proc(float4 v, int e, float& bm, int& bi) {
    float m = fmaxf(fmaxf(v.x, v.y), fmaxf(v.z, v.w));
    if (m > bm) {
        bm = m;
        bi = (m == v.x) ? e : (m == v.y) ? e + 1 : (m == v.z) ? e + 2 : e + 3;
    }
}

__global__ __launch_bounds__(THREADS) void argmax_fused(
    const float* __restrict__ logits, float* __restrict__ out)
{
    const int row   = blockIdx.x / SPLITS;   // 0..63
    const int split = blockIdx.x % SPLITS;   // 0..24

    const float4* __restrict__ p = reinterpret_cast<const float4*>(
        logits + (size_t)row * (SEQ * VOCAB) + (size_t)(SEQ - 1) * VOCAB
               + (size_t)split * SPLIT_FLOATS);

    const int tid = threadIdx.x;
    const int idx_base = split * SPLIT_FLOATS;

    // All 5 loads issued up-front: one memory wave, then compute tail.
    float4 buf[F4_PER_THR];
    #pragma unroll
    for (int u = 0; u < F4_PER_THR; ++u) buf[u] = p[tid + u * THREADS];

    float bm = -__int_as_float(0x7f800000);  // -inf
    int   bi = 0x7fffffff;
    #pragma unroll
    for (int u = 0; u < F4_PER_THR; ++u)
        proc(buf[u], idx_base + (tid + u * THREADS) * 4, bm, bi);

    // intra-warp reduce (full tie-break)
    #pragma unroll
    for (int off = 16; off > 0; off >>= 1) {
        float om = __shfl_down_sync(0xffffffffu, bm, off);
        int   oi = __shfl_down_sync(0xffffffffu, bi, off);
        take_better(om, oi, bm, bi);
    }

    __shared__ float sm[THREADS / 32];  // 8 warps
    __shared__ int   si[THREADS / 32];
    const int lane = tid & 31, warp = tid >> 5;
    if (lane == 0) { sm[warp] = bm; si[warp] = bi; }
    __syncthreads();

    if (warp == 0) {
        bm = (lane < THREADS / 32) ? sm[lane] : -__int_as_float(0x7f800000);
        bi = (lane < THREADS / 32) ? si[lane] : 0x7fffffff;
        #pragma unroll
        for (int off = 4; off > 0; off >>= 1) {
            float om = __shfl_down_sync(0xffffffffu, bm, off);
            int   oi = __shfl_down_sync(0xffffffffu, bi, off);
            take_better(om, oi, bm, bi);
        }
        if (lane == 0) {
            // publish this split's partial
            g_pmax[row * SPLITS + split] = bm;
            g_pidx[row * SPLITS + split] = bi;
            __threadfence();
            int old = atomicAdd(&g_count[row], 1);
            if (old == SPLITS - 1) {
                // last arriver merges all 25 partials (ascending split order:
                // strict > keeps first occurrence on exact ties)
                volatile float* vm = g_pmax + row * SPLITS;
                volatile int*   vi = g_pidx + row * SPLITS;
                float fm = vm[0];
                int   fi = vi[0];
                #pragma unroll 5
                for (int s = 1; s < SPLITS; ++s) {
                    float v = vm[s];
                    int   i = vi[s];
                    if (v > fm) { fm = v; fi = i; }
                }
                out[row] = (float)fi;   // harness compares as float32
                g_count[row] = 0;       // reset for next graph replay
            }
        }
    }
}

extern "C" void kernel_launch(void* const* d_in, const int* in_sizes, int n_in,
                              void* d_out, int out_size) {
    const float* logits = (const float*)d_in[0];
    argmax_fused<<<BATCH * SPLITS, THREADS>>>(logits, (float*)d_out);
}

// round 13
// speedup vs baseline: 1.0173x; 1.0173x over previous
#include <cuda_runtime.h>
#include <cstdint>

// Problem shape (fixed by the reference)
#define BATCH 64
#define SEQ   8
#define VOCAB 128000

// 2 splits/row -> 128 blocks x 256 threads. Each split = 64000 floats = 250KB.
#define SPLITS       2
#define THREADS      256
#define SPLIT_FLOATS (VOCAB / SPLITS)        // 64000
#define SPLIT_F4     (SPLIT_FLOATS / 4)      // 16000

// Bulk-async pipeline: 16 stages of 1000 float4 (16000 B), 3 smem slots.
#define STAGE_F4    1000
#define STAGE_BYTES (STAGE_F4 * 16)          // 16000
#define NSTAGES     (SPLIT_F4 / STAGE_F4)    // 16
#define SLOTS       3

// Scratch (no cudaMalloc allowed). g_count starts 0, reset by last arriver
// each run -> deterministic across graph replays.
__device__ float g_pmax[BATCH * SPLITS];
__device__ int   g_pidx[BATCH * SPLITS];
__device__ int   g_count[BATCH];

__device__ __forceinline__ uint32_t smem_u32(const void* p) {
    uint32_t a;
    asm("{ .reg .u64 t; cvta.to.shared.u64 t, %1; cvt.u32.u64 %0, t; }"
        : "=r"(a) : "l"(p));
    return a;
}

__device__ __forceinline__ void mbar_init(uint32_t mbar, uint32_t cnt) {
    asm volatile("mbarrier.init.shared.b64 [%0], %1;" :: "r"(mbar), "r"(cnt) : "memory");
}
__device__ __forceinline__ void mbar_expect_tx(uint32_t mbar, uint32_t bytes) {
    asm volatile("mbarrier.arrive.expect_tx.shared.b64 _, [%0], %1;"
                 :: "r"(mbar), "r"(bytes) : "memory");
}
__device__ __forceinline__ void mbar_wait(uint32_t mbar, uint32_t parity) {
    asm volatile(
        "{\n\t.reg .pred P;\n"
        "W_%=:\n\t"
        "mbarrier.try_wait.parity.acquire.cta.shared::cta.b64 P, [%0], %1, 0x989680;\n\t"
        "@P bra D_%=;\n\t"
        "bra W_%=;\n"
        "D_%=:\n\t}"
        :: "r"(mbar), "r"(parity) : "memory");
}
// 1D bulk async copy global->shared, completion via mbarrier tx bytes.
__device__ __forceinline__ void bulk_ld(uint32_t dst_smem, const void* src_gmem,
                                        uint32_t bytes, uint32_t mbar) {
    asm volatile(
        "cp.async.bulk.shared::cta.global.mbarrier::complete_tx::bytes [%0], [%1], %2, [%3];"
        :: "r"(dst_smem), "l"(src_gmem), "r"(bytes), "r"(mbar) : "memory");
}

__device__ __forceinline__ void take_better(float v, int i, float& bm, int& bi) {
    // full tie-break (first occurrence = smaller index) for cross-thread merge
    if (v > bm || (v == bm && i < bi)) { bm = v; bi = i; }
}

// In-thread scan: this thread's indices strictly increase -> strict > keeps
// first occurrence. fmaxf tree for ILP; index recovered on rare update.
__device__ __forceinline__ void proc(float4 v, int e, float& bm, int& bi) {
    float m = fmaxf(fmaxf(v.x, v.y), fmaxf(v.z, v.w));
    if (m > bm) {
        bm = m;
        bi = (m == v.x) ? e : (m == v.y) ? e + 1 : (m == v.z) ? e + 2 : e + 3;
    }
}

__global__ __launch_bounds__(THREADS) void argmax_bulk(
    const float* __restrict__ logits, float* __restrict__ out)
{
    __shared__ __align__(16) float4 sbuf[SLOTS][STAGE_F4];   // 48000 B
    __shared__ __align__(8)  unsigned long long mbar_store[SLOTS];
    __shared__ float sm[THREADS / 32];
    __shared__ int   si[THREADS / 32];

    const int row   = blockIdx.x >> 1;      // 0..63
    const int split = blockIdx.x & 1;       // 0..1
    const int tid   = threadIdx.x;

    const char* gsrc = (const char*)(
        logits + (size_t)row * (SEQ * VOCAB) + (size_t)(SEQ - 1) * VOCAB
               + (size_t)split * SPLIT_FLOATS);
    const int idx_base = split * SPLIT_FLOATS;

    uint32_t mb[SLOTS];
    #pragma unroll
    for (int i = 0; i < SLOTS; ++i) mb[i] = smem_u32(&mbar_store[i]);
    uint32_t sb[SLOTS];
    #pragma unroll
    for (int i = 0; i < SLOTS; ++i) sb[i] = smem_u32(&sbuf[i][0]);

    if (tid == 0) {
        #pragma unroll
        for (int i = 0; i < SLOTS; ++i) mbar_init(mb[i], 1);
    }
    __syncthreads();

    // Prefill SLOTS stages
    if (tid == 0) {
        #pragma unroll
        for (int s = 0; s < SLOTS; ++s) {
            mbar_expect_tx(mb[s], STAGE_BYTES);
            bulk_ld(sb[s], gsrc + (size_t)s * STAGE_BYTES, STAGE_BYTES, mb[s]);
        }
    }

    float bm = -__int_as_float(0x7f800000);  // -inf
    int   bi = 0x7fffffff;

    for (int s = 0; s < NSTAGES; ++s) {
        const int slot   = s % SLOTS;
        const int parity = (s / SLOTS) & 1;
        mbar_wait(mb[slot], parity);

        // consume: <=4 float4 per thread, conflict-free LDS.128
        #pragma unroll
        for (int u = 0; u < 4; ++u) {
            const int j = tid + u * THREADS;
            if (j < STAGE_F4) {
                float4 v = sbuf[slot][j];
                proc(v, idx_base + (s * STAGE_F4 + j) * 4, bm, bi);
            }
        }
        __syncthreads();  // all consumed -> slot free
        if (tid == 0 && s + SLOTS < NSTAGES) {
            const int ns = s + SLOTS;     // refill same slot
            mbar_expect_tx(mb[slot], STAGE_BYTES);
            bulk_ld(sb[slot], gsrc + (size_t)ns * STAGE_BYTES, STAGE_BYTES, mb[slot]);
        }
    }

    // intra-warp reduce (full tie-break)
    #pragma unroll
    for (int off = 16; off > 0; off >>= 1) {
        float om = __shfl_down_sync(0xffffffffu, bm, off);
        int   oi = __shfl_down_sync(0xffffffffu, bi, off);
        take_better(om, oi, bm, bi);
    }

    const int lane = tid & 31, warp = tid >> 5;
    if (lane == 0) { sm[warp] = bm; si[warp] = bi; }
    __syncthreads();

    if (warp == 0) {
        bm = (lane < THREADS / 32) ? sm[lane] : -__int_as_float(0x7f800000);
        bi = (lane < THREADS / 32) ? si[lane] : 0x7fffffff;
        #pragma unroll
        for (int off = 4; off > 0; off >>= 1) {
            float om = __shfl_down_sync(0xffffffffu, bm, off);
            int   oi = __shfl_down_sync(0xffffffffu, bi, off);
            take_better(om, oi, bm, bi);
        }
        if (lane == 0) {
            g_pmax[row * SPLITS + split] = bm;
            g_pidx[row * SPLITS + split] = bi;
            __threadfence();
            int old = atomicAdd(&g_count[row], 1);
            if (old == SPLITS - 1) {
                volatile float* vm = g_pmax + row * SPLITS;
                volatile int*   vi = g_pidx + row * SPLITS;
                float fm = vm[0];
                int   fi = vi[0];
                float v1 = vm[1];
                int   i1 = vi[1];
                // split 0 has smaller indices: strict > keeps first occurrence
                if (v1 > fm) { fm = v1; fi = i1; }
                out[row] = (float)fi;   // harness compares as float32
                g_count[row] = 0;       // reset for next graph replay
            }
        }
    }
}

extern "C" void kernel_launch(void* const* d_in, const int* in_sizes, int n_in,
                              void* d_out, int out_size) {
    const float* logits = (const float*)d_in[0];
    argmax_bulk<<<BATCH * SPLITS, THREADS>>>(logits, (float*)d_out);
}

// round 14
// speedup vs baseline: 1.4018x; 1.3780x over previous
#include <cuda_runtime.h>
#include <cstdint>

// Problem shape (fixed by the reference)
#define BATCH 64
#define SEQ   8
#define VOCAB 128000

// 5 splits/row -> 320 blocks x 256 threads (8 warps).
// Split = 25600 floats = 6400 float4 -> exactly 25 f4/thread = 5 batches of 5.
#define SPLITS       5
#define THREADS      256
#define SPLIT_FLOATS (VOCAB / SPLITS)        // 25600
#define SPLIT_F4     (SPLIT_FLOATS / 4)      // 6400
#define BATCHES      5
#define BW_          5                        // f4 per batch per thread

// Scratch (no cudaMalloc allowed). g_count starts 0, reset by last arriver
// each run -> deterministic across graph replays.
__device__ float g_pmax[BATCH * SPLITS];
__device__ int   g_pidx[BATCH * SPLITS];
__device__ int   g_count[BATCH];

__device__ __forceinline__ void take_better(float v, int i, float& bm, int& bi) {
    // full tie-break (first occurrence = smaller index) for cross-thread merge
    if (v > bm || (v == bm && i < bi)) { bm = v; bi = i; }
}

// In-thread scan: this thread's indices strictly increase -> strict > keeps
// first occurrence. fmaxf tree for ILP; index recovered on rare update.
__device__ __forceinline__ void proc(float4 v, int e, float& bm, int& bi) {
    float m = fmaxf(fmaxf(v.x, v.y), fmaxf(v.z, v.w));
    if (m > bm) {
        bm = m;
        bi = (m == v.x) ? e : (m == v.y) ? e + 1 : (m == v.z) ? e + 2 : e + 3;
    }
}

__global__ __launch_bounds__(THREADS, 5) void argmax_occ(
    const float* __restrict__ logits, float* __restrict__ out)
{
    const int row   = blockIdx.x / SPLITS;   // 0..63
    const int split = blockIdx.x % SPLITS;   // 0..4

    const float4* __restrict__ p = reinterpret_cast<const float4*>(
        logits + (size_t)row * (SEQ * VOCAB) + (size_t)(SEQ - 1) * VOCAB
               + (size_t)split * SPLIT_FLOATS);

    const int tid = threadIdx.x;
    const int idx_base = split * SPLIT_FLOATS;

    float bm = -__int_as_float(0x7f800000);  // -inf
    int   bi = 0x7fffffff;

    // 5 batches x 5 float4: rolling load stream, 5 LDG.128 in flight/thread.
    float4 buf[BW_];
    #pragma unroll
    for (int b = 0; b < BATCHES; ++b) {
        #pragma unroll
        for (int u = 0; u < BW_; ++u)
            buf[u] = p[tid + (b * BW_ + u) * THREADS];
        #pragma unroll
        for (int u = 0; u < BW_; ++u)
            proc(buf[u], idx_base + (tid + (b * BW_ + u) * THREADS) * 4, bm, bi);
    }

    // intra-warp reduce (full tie-break)
    #pragma unroll
    for (int off = 16; off > 0; off >>= 1) {
        float om = __shfl_down_sync(0xffffffffu, bm, off);
        int   oi = __shfl_down_sync(0xffffffffu, bi, off);
        take_better(om, oi, bm, bi);
    }

    __shared__ float sm[THREADS / 32];  // 8 warps
    __shared__ int   si[THREADS / 32];
    const int lane = tid & 31, warp = tid >> 5;
    if (lane == 0) { sm[warp] = bm; si[warp] = bi; }
    __syncthreads();

    if (warp == 0) {
        bm = (lane < THREADS / 32) ? sm[lane] : -__int_as_float(0x7f800000);
        bi = (lane < THREADS / 32) ? si[lane] : 0x7fffffff;
        #pragma unroll
        for (int off = 4; off > 0; off >>= 1) {
            float om = __shfl_down_sync(0xffffffffu, bm, off);
            int   oi = __shfl_down_sync(0xffffffffu, bi, off);
            take_better(om, oi, bm, bi);
        }
        if (lane == 0) {
            // publish this split's partial
            g_pmax[row * SPLITS + split] = bm;
            g_pidx[row * SPLITS + split] = bi;
            __threadfence();
            int old = atomicAdd(&g_count[row], 1);
            if (old == SPLITS - 1) {
                // last arriver merges (ascending split order: strict > keeps
                // first occurrence on exact ties)
                volatile float* vm = g_pmax + row * SPLITS;
                volatile int*   vi = g_pidx + row * SPLITS;
                float fm = vm[0];
                int   fi = vi[0];
                #pragma unroll
                for (int s = 1; s < SPLITS; ++s) {
                    float v = vm[s];
                    int   i = vi[s];
                    if (v > fm) { fm = v; fi = i; }
                }
                out[row] = (float)fi;   // harness compares as float32
                g_count[row] = 0;       // reset for next graph replay
            }
        }
    }
}

extern "C" void kernel_launch(void* const* d_in, const int* in_sizes, int n_in,
                              void* d_out, int out_size) {
    const float* logits = (const float*)d_in[0];
    argmax_occ<<<BATCH * SPLITS, THREADS>>>(logits, (float*)d_out);
}